// round 3
// baseline (speedup 1.0000x reference)
#include <cuda_runtime.h>
#include <cstdint>

// CosinePrediction: cos[e] = <u[src[e]], v[dst[e]]> / (||u||*||v||)
// D = 64 floats per row. 16 threads per edge, one float4 per lane per row.
// Indices are int32 (JAX x64 disabled downcasts the reference's int64).

static constexpr int D = 64;
static constexpr int LANES_PER_EDGE = 16;   // 16 lanes * float4 = 64 floats
static constexpr int THREADS = 256;         // 16 edges per block

__global__ __launch_bounds__(THREADS) void cosine_edge_kernel(
    const float* __restrict__ h_user,
    const float* __restrict__ h_item,
    const int* __restrict__ src_idx,
    const int* __restrict__ dst_idx,
    float* __restrict__ out,
    int E)
{
    const int gid  = blockIdx.x * THREADS + threadIdx.x;
    const int e    = gid >> 4;          // edge index
    const int lane = gid & 15;          // lane within edge group
    if (e >= E) return;

    const int s = __ldg(src_idx + e);
    const int d = __ldg(dst_idx + e);

    const float4 u = __ldg(reinterpret_cast<const float4*>(h_user + (long long)s * D) + lane);
    const float4 v = __ldg(reinterpret_cast<const float4*>(h_item + (long long)d * D) + lane);

    float dot = u.x * v.x + u.y * v.y + u.z * v.z + u.w * v.w;
    float nu  = u.x * u.x + u.y * u.y + u.z * u.z + u.w * u.w;
    float nv  = v.x * v.x + v.y * v.y + v.z * v.z + v.w * v.w;

    // Reduce across the 16-lane edge group (groups are aligned, xor stays inside).
    #pragma unroll
    for (int o = 8; o > 0; o >>= 1) {
        dot += __shfl_xor_sync(0xFFFFFFFFu, dot, o);
        nu  += __shfl_xor_sync(0xFFFFFFFFu, nu,  o);
        nv  += __shfl_xor_sync(0xFFFFFFFFu, nv,  o);
    }

    if (lane == 0) {
        out[e] = dot * rsqrtf(nu) * rsqrtf(nv);
    }
}

extern "C" void kernel_launch(void* const* d_in, const int* in_sizes, int n_in,
                              void* d_out, int out_size)
{
    const float* h_user = (const float*)d_in[0];
    const float* h_item = (const float*)d_in[1];
    const int*   src    = (const int*)d_in[2];
    const int*   dst    = (const int*)d_in[3];
    float*       out    = (float*)d_out;

    const int E = in_sizes[2];  // number of edges

    const long long total_threads = (long long)E * LANES_PER_EDGE;
    const int blocks = (int)((total_threads + THREADS - 1) / THREADS);

    cosine_edge_kernel<<<blocks, THREADS>>>(h_user, h_item, src, dst, out, E);
}

// round 4
// speedup vs baseline: 1.5766x; 1.5766x over previous
#include <cuda_runtime.h>
#include <cstdint>

// CosinePrediction: cos[e] = <u[src[e]], v[dst[e]]> / (||u||*||v||)
// D = 64 floats per row. 8 lanes per edge, two float4s per lane.
// Each LDG.128 warp-instruction covers exactly full 128B lines -> minimal
// L1 wavefronts (2 per 256B row). 3-step butterfly instead of 4.

static constexpr int D = 64;
static constexpr int THREADS = 256;   // 32 edges per block (8 lanes/edge)

__global__ __launch_bounds__(THREADS) void cosine_edge_kernel(
    const float* __restrict__ h_user,
    const float* __restrict__ h_item,
    const int* __restrict__ src_idx,
    const int* __restrict__ dst_idx,
    float* __restrict__ out,
    int E)
{
    const int gid  = blockIdx.x * THREADS + threadIdx.x;
    const int e    = gid >> 3;          // edge index
    const int lane = gid & 7;           // lane within 8-lane edge group
    if (e >= E) return;

    const int s = __ldg(src_idx + e);
    const int d = __ldg(dst_idx + e);

    const float4* __restrict__ urow = reinterpret_cast<const float4*>(h_user + (long long)s * D);
    const float4* __restrict__ vrow = reinterpret_cast<const float4*>(h_item + (long long)d * D);

    // 4 independent loads in flight per thread (good MLP).
    const float4 u0 = __ldg(urow + lane);
    const float4 u1 = __ldg(urow + lane + 8);
    const float4 v0 = __ldg(vrow + lane);
    const float4 v1 = __ldg(vrow + lane + 8);

    float dot = u0.x * v0.x;
    dot = fmaf(u0.y, v0.y, dot);
    dot = fmaf(u0.z, v0.z, dot);
    dot = fmaf(u0.w, v0.w, dot);
    dot = fmaf(u1.x, v1.x, dot);
    dot = fmaf(u1.y, v1.y, dot);
    dot = fmaf(u1.z, v1.z, dot);
    dot = fmaf(u1.w, v1.w, dot);

    float nu = u0.x * u0.x;
    nu = fmaf(u0.y, u0.y, nu);
    nu = fmaf(u0.z, u0.z, nu);
    nu = fmaf(u0.w, u0.w, nu);
    nu = fmaf(u1.x, u1.x, nu);
    nu = fmaf(u1.y, u1.y, nu);
    nu = fmaf(u1.z, u1.z, nu);
    nu = fmaf(u1.w, u1.w, nu);

    float nv = v0.x * v0.x;
    nv = fmaf(v0.y, v0.y, nv);
    nv = fmaf(v0.z, v0.z, nv);
    nv = fmaf(v0.w, v0.w, nv);
    nv = fmaf(v1.x, v1.x, nv);
    nv = fmaf(v1.y, v1.y, nv);
    nv = fmaf(v1.z, v1.z, nv);
    nv = fmaf(v1.w, v1.w, nv);

    // 3-step butterfly within each 8-lane group (groups aligned; xor stays inside).
    #pragma unroll
    for (int o = 4; o > 0; o >>= 1) {
        dot += __shfl_xor_sync(0xFFFFFFFFu, dot, o);
        nu  += __shfl_xor_sync(0xFFFFFFFFu, nu,  o);
        nv  += __shfl_xor_sync(0xFFFFFFFFu, nv,  o);
    }

    if (lane == 0) {
        out[e] = dot * rsqrtf(nu * nv);   // single MUFU
    }
}

extern "C" void kernel_launch(void* const* d_in, const int* in_sizes, int n_in,
                              void* d_out, int out_size)
{
    const float* h_user = (const float*)d_in[0];
    const float* h_item = (const float*)d_in[1];
    const int*   src    = (const int*)d_in[2];
    const int*   dst    = (const int*)d_in[3];
    float*       out    = (float*)d_out;

    const int E = in_sizes[2];  // number of edges

    const long long total_threads = (long long)E * 8;
    const int blocks = (int)((total_threads + THREADS - 1) / THREADS);

    cosine_edge_kernel<<<blocks, THREADS>>>(h_user, h_item, src, dst, out, E);
}

// round 5
// speedup vs baseline: 1.6859x; 1.0694x over previous
#include <cuda_runtime.h>
#include <cstdint>

// CosinePrediction: cos[e] = <u[src[e]], v[dst[e]]> / (||u||*||v||)
// D = 64 floats per row. 8 lanes per EDGE-PAIR: each thread handles 2 edges
// (2g, 2g+1), two float4s per row half -> 8 independent LDG.128 in flight
// per thread (MLP=8). Adjacent outputs let lane 0 do one float2 store.

static constexpr int D = 64;
static constexpr int THREADS = 256;   // 8 lanes/edge, 2 edges/thread -> 64 edges per block

__global__ __launch_bounds__(THREADS) void cosine_edge_kernel(
    const float* __restrict__ h_user,
    const float* __restrict__ h_item,
    const int* __restrict__ src_idx,
    const int* __restrict__ dst_idx,
    float* __restrict__ out,
    int E)
{
    const int gid   = blockIdx.x * THREADS + threadIdx.x;
    const int g     = gid >> 3;          // edge-pair index
    const int lane  = gid & 7;           // lane within 8-lane group
    const int e0    = g * 2;
    if (e0 >= E) return;
    const bool have1 = (e0 + 1) < E;     // E is even in practice; guard anyway

    // Broadcast index loads: all 8 lanes read the same int2.
    const int2 sp = __ldg(reinterpret_cast<const int2*>(src_idx + e0));
    const int2 dp = __ldg(reinterpret_cast<const int2*>(dst_idx + e0));

    const float4* __restrict__ ua = reinterpret_cast<const float4*>(h_user + (long long)sp.x * D);
    const float4* __restrict__ va = reinterpret_cast<const float4*>(h_item + (long long)dp.x * D);
    const float4* __restrict__ ub = reinterpret_cast<const float4*>(h_user + (long long)sp.y * D);
    const float4* __restrict__ vb = reinterpret_cast<const float4*>(h_item + (long long)dp.y * D);

    // 8 independent loads in flight.
    const float4 ua0 = __ldg(ua + lane);
    const float4 ua1 = __ldg(ua + lane + 8);
    const float4 va0 = __ldg(va + lane);
    const float4 va1 = __ldg(va + lane + 8);
    const float4 ub0 = __ldg(ub + lane);
    const float4 ub1 = __ldg(ub + lane + 8);
    const float4 vb0 = __ldg(vb + lane);
    const float4 vb1 = __ldg(vb + lane + 8);

    // Edge 0 accumulators
    float dotA = ua0.x * va0.x;
    dotA = fmaf(ua0.y, va0.y, dotA);
    dotA = fmaf(ua0.z, va0.z, dotA);
    dotA = fmaf(ua0.w, va0.w, dotA);
    dotA = fmaf(ua1.x, va1.x, dotA);
    dotA = fmaf(ua1.y, va1.y, dotA);
    dotA = fmaf(ua1.z, va1.z, dotA);
    dotA = fmaf(ua1.w, va1.w, dotA);

    float nuA = ua0.x * ua0.x;
    nuA = fmaf(ua0.y, ua0.y, nuA);
    nuA = fmaf(ua0.z, ua0.z, nuA);
    nuA = fmaf(ua0.w, ua0.w, nuA);
    nuA = fmaf(ua1.x, ua1.x, nuA);
    nuA = fmaf(ua1.y, ua1.y, nuA);
    nuA = fmaf(ua1.z, ua1.z, nuA);
    nuA = fmaf(ua1.w, ua1.w, nuA);

    float nvA = va0.x * va0.x;
    nvA = fmaf(va0.y, va0.y, nvA);
    nvA = fmaf(va0.z, va0.z, nvA);
    nvA = fmaf(va0.w, va0.w, nvA);
    nvA = fmaf(va1.x, va1.x, nvA);
    nvA = fmaf(va1.y, va1.y, nvA);
    nvA = fmaf(va1.z, va1.z, nvA);
    nvA = fmaf(va1.w, va1.w, nvA);

    // Edge 1 accumulators
    float dotB = ub0.x * vb0.x;
    dotB = fmaf(ub0.y, vb0.y, dotB);
    dotB = fmaf(ub0.z, vb0.z, dotB);
    dotB = fmaf(ub0.w, vb0.w, dotB);
    dotB = fmaf(ub1.x, vb1.x, dotB);
    dotB = fmaf(ub1.y, vb1.y, dotB);
    dotB = fmaf(ub1.z, vb1.z, dotB);
    dotB = fmaf(ub1.w, vb1.w, dotB);

    float nuB = ub0.x * ub0.x;
    nuB = fmaf(ub0.y, ub0.y, nuB);
    nuB = fmaf(ub0.z, ub0.z, nuB);
    nuB = fmaf(ub0.w, ub0.w, nuB);
    nuB = fmaf(ub1.x, ub1.x, nuB);
    nuB = fmaf(ub1.y, ub1.y, nuB);
    nuB = fmaf(ub1.z, ub1.z, nuB);
    nuB = fmaf(ub1.w, ub1.w, nuB);

    float nvB = vb0.x * vb0.x;
    nvB = fmaf(vb0.y, vb0.y, nvB);
    nvB = fmaf(vb0.z, vb0.z, nvB);
    nvB = fmaf(vb0.w, vb0.w, nvB);
    nvB = fmaf(vb1.x, vb1.x, nvB);
    nvB = fmaf(vb1.y, vb1.y, nvB);
    nvB = fmaf(vb1.z, vb1.z, nvB);
    nvB = fmaf(vb1.w, vb1.w, nvB);

    // 3-step butterfly within each aligned 8-lane group.
    #pragma unroll
    for (int o = 4; o > 0; o >>= 1) {
        dotA += __shfl_xor_sync(0xFFFFFFFFu, dotA, o);
        nuA  += __shfl_xor_sync(0xFFFFFFFFu, nuA,  o);
        nvA  += __shfl_xor_sync(0xFFFFFFFFu, nvA,  o);
        dotB += __shfl_xor_sync(0xFFFFFFFFu, dotB, o);
        nuB  += __shfl_xor_sync(0xFFFFFFFFu, nuB,  o);
        nvB  += __shfl_xor_sync(0xFFFFFFFFu, nvB,  o);
    }

    if (lane == 0) {
        const float cA = dotA * rsqrtf(nuA * nvA);
        const float cB = dotB * rsqrtf(nuB * nvB);
        if (have1) {
            float2 r; r.x = cA; r.y = cB;
            *reinterpret_cast<float2*>(out + e0) = r;   // single STG.64
        } else {
            out[e0] = cA;
        }
    }
}

extern "C" void kernel_launch(void* const* d_in, const int* in_sizes, int n_in,
                              void* d_out, int out_size)
{
    const float* h_user = (const float*)d_in[0];
    const float* h_item = (const float*)d_in[1];
    const int*   src    = (const int*)d_in[2];
    const int*   dst    = (const int*)d_in[3];
    float*       out    = (float*)d_out;

    const int E = in_sizes[2];  // number of edges

    const int pairs = (E + 1) / 2;
    const long long total_threads = (long long)pairs * 8;
    const int blocks = (int)((total_threads + THREADS - 1) / THREADS);

    cosine_edge_kernel<<<blocks, THREADS>>>(h_user, h_item, src, dst, out, E);
}